// round 1
// baseline (speedup 1.0000x reference)
#include <cuda_runtime.h>
#include <math.h>

// Level 0: [4, 64, 4096], level 1: [4, 128, 1024]
#define NTILE0 64                       // 4096 / 64
#define NTILE1 16                       // 1024 / 64
#define NBLK0 (NTILE0 * (NTILE0 + 1) / 2)   // 2080 upper-tri tiles
#define NBLK1 (NTILE1 * (NTILE1 + 1) / 2)   // 136

// Fixed-slot per-block partial sums -> fully deterministic reduction, no atomics.
__device__ double g_part[NBLK0 + NBLK1];

// Fused gram + batch-softmax + |A1-A2| tile kernel.
// One block computes one 64x64 (i,j) tile of the symmetric gram, for all
// 8 (feature, batch) combos, then the softmax/abs-diff epilogue in registers.
// Upper triangle only: off-diagonal elements weighted 2x.
template<int C, int HW, int LVL_OFF>
__global__ __launch_bounds__(256, 1)
void gram_loss_kernel(const float* __restrict__ f1, const float* __restrict__ f2)
{
    constexpr int NT = HW / 64;
    constexpr int KC = 8;

    __shared__ float sA[8][KC][64];   // [combo][k][i]
    __shared__ float sB[8][KC][64];   // [combo][k][j]

    // blockIdx.x -> (ti, tj) with ti <= tj (row-major upper triangle)
    int rem = blockIdx.x;
    int ti = 0;
    while (rem >= NT - ti) { rem -= NT - ti; ti++; }
    const int tj = ti + rem;
    const int I0 = ti * 64;
    const int J0 = tj * 64;

    const int tid = threadIdx.x;
    const int tx = tid & 15;    // j direction, 16 threads
    const int ty = tid >> 4;    // i direction, 16 threads

    float acc[8][16];
    #pragma unroll
    for (int c = 0; c < 8; c++)
        #pragma unroll
        for (int p = 0; p < 16; p++) acc[c][p] = 0.f;

    for (int k0 = 0; k0 < C; k0 += KC) {
        // Stage operand tiles: 8 combos x KC x 64 floats per side.
        // 1024 float4 per side, 4 per thread.
        #pragma unroll
        for (int it = 0; it < 4; it++) {
            int l     = it * 256 + tid;
            int i4    = l & 15;             // float4 index within a 64-float row
            int kk    = (l >> 4) & (KC - 1);
            int combo = l >> 7;             // 0..7
            const float* base = (combo < 4) ? f1 : f2;
            int b = combo & 3;
            size_t row = (size_t)b * C * HW + (size_t)(k0 + kk) * HW;
            float4 va = ((const float4*)(base + row + I0))[i4];
            float4 vb = ((const float4*)(base + row + J0))[i4];
            *(float4*)&sA[combo][kk][i4 * 4] = va;
            *(float4*)&sB[combo][kk][i4 * 4] = vb;
        }
        __syncthreads();

        #pragma unroll
        for (int kk = 0; kk < KC; kk++) {
            #pragma unroll
            for (int c = 0; c < 8; c++) {
                float4 av = *(const float4*)&sA[c][kk][ty * 4];
                float4 bv = *(const float4*)&sB[c][kk][tx * 4];
                float a_[4] = {av.x, av.y, av.z, av.w};
                float b_[4] = {bv.x, bv.y, bv.z, bv.w};
                #pragma unroll
                for (int ii = 0; ii < 4; ii++)
                    #pragma unroll
                    for (int jj = 0; jj < 4; jj++)
                        acc[c][ii * 4 + jj] = fmaf(a_[ii], b_[jj], acc[c][ii * 4 + jj]);
            }
        }
        __syncthreads();
    }

    // Epilogue: per (i,j) softmax over batch (stable), abs-diff, weighted sum.
    float lsum = 0.f;
    #pragma unroll
    for (int ii = 0; ii < 4; ii++) {
        const int gi = I0 + ty * 4 + ii;
        #pragma unroll
        for (int jj = 0; jj < 4; jj++) {
            const int gj = J0 + tx * 4 + jj;
            float w = (gi < gj) ? 2.f : ((gi == gj) ? 1.f : 0.f);
            if (w == 0.f) continue;   // lower triangle of diagonal tiles
            const int p = ii * 4 + jj;
            float x0 = acc[0][p], x1 = acc[1][p], x2 = acc[2][p], x3 = acc[3][p];
            float y0 = acc[4][p], y1 = acc[5][p], y2 = acc[6][p], y3 = acc[7][p];
            float m1 = fmaxf(fmaxf(x0, x1), fmaxf(x2, x3));
            float m2 = fmaxf(fmaxf(y0, y1), fmaxf(y2, y3));
            float e0 = __expf(x0 - m1), e1 = __expf(x1 - m1);
            float e2 = __expf(x2 - m1), e3 = __expf(x3 - m1);
            float h0 = __expf(y0 - m2), h1 = __expf(y1 - m2);
            float h2 = __expf(y2 - m2), h3 = __expf(y3 - m2);
            float s1 = 1.0f / (e0 + e1 + e2 + e3);
            float s2 = 1.0f / (h0 + h1 + h2 + h3);
            lsum += w * (fabsf(e0 * s1 - h0 * s2) + fabsf(e1 * s1 - h1 * s2)
                       + fabsf(e2 * s1 - h2 * s2) + fabsf(e3 * s1 - h3 * s2));
        }
    }

    // Block reduction -> fixed partial slot.
    #pragma unroll
    for (int o = 16; o > 0; o >>= 1) lsum += __shfl_xor_sync(0xffffffffu, lsum, o);
    __shared__ float red[8];
    if ((tid & 31) == 0) red[tid >> 5] = lsum;
    __syncthreads();
    if (tid == 0) {
        float bs = 0.f;
        #pragma unroll
        for (int r = 0; r < 8; r++) bs += red[r];
        g_part[LVL_OFF + blockIdx.x] = (double)bs;
    }
}

__global__ void finalize_kernel(float* __restrict__ out)
{
    __shared__ double sd[256];
    const int tid = threadIdx.x;
    const double w0 = 0.5 / (4.0 * 4096.0 * 4096.0);
    const double w1 = 0.5 / (4.0 * 1024.0 * 1024.0);
    double s = 0.0;
    for (int i = tid; i < NBLK0; i += 256) s += g_part[i] * w0;
    for (int i = tid; i < NBLK1; i += 256) s += g_part[NBLK0 + i] * w1;
    sd[tid] = s;
    __syncthreads();
    for (int o = 128; o > 0; o >>= 1) {
        if (tid < o) sd[tid] += sd[tid + o];
        __syncthreads();
    }
    if (tid == 0) out[0] = (float)sd[0];
}

extern "C" void kernel_launch(void* const* d_in, const int* in_sizes, int n_in,
                              void* d_out, int out_size)
{
    const float* fea1_0 = (const float*)d_in[0];  // [4, 64, 64, 64]
    const float* fea1_1 = (const float*)d_in[1];  // [4, 128, 32, 32]
    const float* fea2_0 = (const float*)d_in[2];
    const float* fea2_1 = (const float*)d_in[3];
    float* out = (float*)d_out;

    gram_loss_kernel<64, 4096, 0><<<NBLK0, 256>>>(fea1_0, fea2_0);
    gram_loss_kernel<128, 1024, NBLK0><<<NBLK1, 256>>>(fea1_1, fea2_1);
    finalize_kernel<<<1, 256>>>(out);
}

// round 2
// speedup vs baseline: 1.1292x; 1.1292x over previous
#include <cuda_runtime.h>
#include <math.h>

// Level 0: [4, 64, 4096], level 1: [4, 128, 1024]
#define NTILE0 64                       // 4096 / 64
#define NTILE1 16                       // 1024 / 64
#define NBLK0 (NTILE0 * (NTILE0 + 1) / 2)   // 2080 upper-tri tiles
#define NBLK1 (NTILE1 * (NTILE1 + 1) / 2)   // 136
#define KC 8

// Fixed-slot per-block partials -> deterministic reduction, no atomics.
__device__ double g_part[NBLK0 + NBLK1];

// ---- packed f32x2 helpers (Blackwell FFMA2 path; ptxas never emits these from C++) ----
__device__ __forceinline__ unsigned long long pack2(float lo, float hi) {
    unsigned long long r;
    asm("mov.b64 %0, {%1, %2};" : "=l"(r) : "f"(lo), "f"(hi));
    return r;
}
__device__ __forceinline__ void unpack2(unsigned long long v, float& lo, float& hi) {
    asm("mov.b64 {%0, %1}, %2;" : "=f"(lo), "=f"(hi) : "l"(v));
}
__device__ __forceinline__ unsigned long long ffma2(unsigned long long a,
                                                    unsigned long long b,
                                                    unsigned long long c) {
    unsigned long long r;
    asm("fma.rn.f32x2 %0, %1, %2, %3;" : "=l"(r) : "l"(a), "l"(b), "l"(c));
    return r;
}
// Load an aligned float pair from shared memory directly into a 64-bit reg (no pack).
__device__ __forceinline__ unsigned long long lds64(const float* p) {
    unsigned long long r;
    unsigned s = (unsigned)__cvta_generic_to_shared(p);
    asm("ld.shared.b64 %0, [%1];" : "=l"(r) : "r"(s));
    return r;
}

// One 64x64 (i,j) upper-tri tile of the symmetric gram, all 8 (feature,batch)
// combos, fused batch-softmax + |A1-A2| epilogue. FFMA2 inner loop.
template<int C, int HW, int LVL_OFF>
__device__ __forceinline__ void gram_tile(const float* __restrict__ f1,
                                          const float* __restrict__ f2,
                                          int blk, float* smem)
{
    constexpr int NT = HW / 64;
    float* sA = smem;                 // [8][KC][64]
    float* sB = smem + 8 * KC * 64;   // [8][KC][64]

    int rem = blk, ti = 0;
    while (rem >= NT - ti) { rem -= NT - ti; ti++; }
    const int tj = ti + rem;
    const int I0 = ti * 64;
    const int J0 = tj * 64;

    const int tid = threadIdx.x;
    const int tx = tid & 15;    // j direction
    const int ty = tid >> 4;    // i direction

    // acc[c][ii*2 + jp] = packed pair for (ii, jj = 2*jp .. 2*jp+1)
    unsigned long long acc[8][8];
    #pragma unroll
    for (int c = 0; c < 8; c++)
        #pragma unroll
        for (int p = 0; p < 8; p++) acc[c][p] = 0ull;

    for (int k0 = 0; k0 < C; k0 += KC) {
        // Stage 8 combos x KC x 64 floats per side (4 float4 per thread per side).
        #pragma unroll
        for (int it = 0; it < 4; it++) {
            int l     = it * 256 + tid;
            int i4    = l & 15;
            int kk    = (l >> 4) & (KC - 1);
            int combo = l >> 7;
            const float* base = (combo < 4) ? f1 : f2;
            int b = combo & 3;
            size_t row = (size_t)b * C * HW + (size_t)(k0 + kk) * HW;
            float4 va = ((const float4*)(base + row + I0))[i4];
            float4 vb = ((const float4*)(base + row + J0))[i4];
            *(float4*)&sA[(combo * KC + kk) * 64 + i4 * 4] = va;
            *(float4*)&sB[(combo * KC + kk) * 64 + i4 * 4] = vb;
        }
        __syncthreads();

        #pragma unroll
        for (int kk = 0; kk < KC; kk++) {
            #pragma unroll
            for (int c = 0; c < 8; c++) {
                const float* pa = &sA[(c * KC + kk) * 64 + ty * 4];
                const float* pb = &sB[(c * KC + kk) * 64 + tx * 4];
                float4 av = *(const float4*)pa;
                unsigned long long B0 = lds64(pb);
                unsigned long long B1 = lds64(pb + 2);
                unsigned long long A0 = pack2(av.x, av.x);
                unsigned long long A1 = pack2(av.y, av.y);
                unsigned long long A2 = pack2(av.z, av.z);
                unsigned long long A3 = pack2(av.w, av.w);
                acc[c][0] = ffma2(A0, B0, acc[c][0]);
                acc[c][1] = ffma2(A0, B1, acc[c][1]);
                acc[c][2] = ffma2(A1, B0, acc[c][2]);
                acc[c][3] = ffma2(A1, B1, acc[c][3]);
                acc[c][4] = ffma2(A2, B0, acc[c][4]);
                acc[c][5] = ffma2(A2, B1, acc[c][5]);
                acc[c][6] = ffma2(A3, B0, acc[c][6]);
                acc[c][7] = ffma2(A3, B1, acc[c][7]);
            }
        }
        __syncthreads();
    }

    // Epilogue: per (i,j) stable softmax over batch, abs-diff, weighted sum.
    float lsum = 0.f;
    #pragma unroll
    for (int ii = 0; ii < 4; ii++) {
        const int gi = I0 + ty * 4 + ii;
        #pragma unroll
        for (int jp = 0; jp < 2; jp++) {
            float x[8], y[8];   // x: lo lane (jj=2*jp), y: hi lane (jj=2*jp+1)
            #pragma unroll
            for (int c = 0; c < 8; c++) unpack2(acc[c][ii * 2 + jp], x[c], y[c]);

            #pragma unroll
            for (int half = 0; half < 2; half++) {
                const int gj = J0 + tx * 4 + jp * 2 + half;
                float w = (gi < gj) ? 2.f : ((gi == gj) ? 1.f : 0.f);
                if (w == 0.f) continue;
                const float* v = half ? y : x;
                float m1 = fmaxf(fmaxf(v[0], v[1]), fmaxf(v[2], v[3]));
                float m2 = fmaxf(fmaxf(v[4], v[5]), fmaxf(v[6], v[7]));
                float e0 = __expf(v[0] - m1), e1 = __expf(v[1] - m1);
                float e2 = __expf(v[2] - m1), e3 = __expf(v[3] - m1);
                float h0 = __expf(v[4] - m2), h1 = __expf(v[5] - m2);
                float h2 = __expf(v[6] - m2), h3 = __expf(v[7] - m2);
                float s1 = 1.0f / (e0 + e1 + e2 + e3);
                float s2 = 1.0f / (h0 + h1 + h2 + h3);
                lsum += w * (fabsf(e0 * s1 - h0 * s2) + fabsf(e1 * s1 - h1 * s2)
                           + fabsf(e2 * s1 - h2 * s2) + fabsf(e3 * s1 - h3 * s2));
            }
        }
    }

    // Block reduction -> fixed partial slot.
    #pragma unroll
    for (int o = 16; o > 0; o >>= 1) lsum += __shfl_xor_sync(0xffffffffu, lsum, o);
    __shared__ float red[8];
    if ((tid & 31) == 0) red[tid >> 5] = lsum;
    __syncthreads();
    if (tid == 0) {
        float bs = 0.f;
        #pragma unroll
        for (int r = 0; r < 8; r++) bs += red[r];
        g_part[LVL_OFF + blk] = (double)bs;
    }
}

// Both levels in one launch so level-1 blocks fill level-0's tail wave.
__global__ __launch_bounds__(256, 1)
void fused_gram_loss_kernel(const float* __restrict__ f1_0, const float* __restrict__ f2_0,
                            const float* __restrict__ f1_1, const float* __restrict__ f2_1)
{
    __shared__ float smem[2 * 8 * KC * 64];   // 32 KB
    if (blockIdx.x < NBLK0)
        gram_tile<64, 4096, 0>(f1_0, f2_0, blockIdx.x, smem);
    else
        gram_tile<128, 1024, NBLK0>(f1_1, f2_1, blockIdx.x - NBLK0, smem);
}

__global__ void finalize_kernel(float* __restrict__ out)
{
    __shared__ double sd[256];
    const int tid = threadIdx.x;
    const double w0 = 0.5 / (4.0 * 4096.0 * 4096.0);
    const double w1 = 0.5 / (4.0 * 1024.0 * 1024.0);
    double s = 0.0;
    for (int i = tid; i < NBLK0; i += 256) s += g_part[i] * w0;
    for (int i = tid; i < NBLK1; i += 256) s += g_part[NBLK0 + i] * w1;
    sd[tid] = s;
    __syncthreads();
    for (int o = 128; o > 0; o >>= 1) {
        if (tid < o) sd[tid] += sd[tid + o];
        __syncthreads();
    }
    if (tid == 0) out[0] = (float)sd[0];
}

extern "C" void kernel_launch(void* const* d_in, const int* in_sizes, int n_in,
                              void* d_out, int out_size)
{
    const float* fea1_0 = (const float*)d_in[0];  // [4, 64, 64, 64]
    const float* fea1_1 = (const float*)d_in[1];  // [4, 128, 32, 32]
    const float* fea2_0 = (const float*)d_in[2];
    const float* fea2_1 = (const float*)d_in[3];
    float* out = (float*)d_out;

    fused_gram_loss_kernel<<<NBLK0 + NBLK1, 256>>>(fea1_0, fea2_0, fea1_1, fea2_1);
    finalize_kernel<<<1, 256>>>(out);
}

// round 4
// speedup vs baseline: 1.5559x; 1.3779x over previous
#include <cuda_runtime.h>
#include <cstdint>
#include <math.h>

// Level 0: [4, 64, 4096], level 1: [4, 128, 1024]; 64x64 upper-tri tiles.
#define NTILE0 64
#define NTILE1 16
#define NBLK0 (NTILE0 * (NTILE0 + 1) / 2)   // 2080
#define NBLK1 (NTILE1 * (NTILE1 + 1) / 2)   // 136

#define KC 16                         // k-rows staged per chunk
#define PADS 68                       // floats per k-row (64 + 4 pad -> <=2-way LDS conflicts)
#define SIDE_STRIDE (KC * PADS)       // 1088 floats per combo per side
#define SMEM_FLOATS (16 * SIDE_STRIDE)  // A(8 combos) + B(8 combos)
#define SMEM_BYTES (SMEM_FLOATS * 4)    // 69632 B

__device__ double g_part[NBLK0 + NBLK1];

__device__ __forceinline__ uint32_t cvt_tf32(float x) {
    uint32_t r;
    asm("cvt.rna.tf32.f32 %0, %1;" : "=r"(r) : "f"(x));
    return r;
}
__device__ __forceinline__ void mma_tf32(float* d, const uint32_t* a, const uint32_t* b) {
    asm volatile(
        "mma.sync.aligned.m16n8k8.row.col.f32.tf32.tf32.f32 "
        "{%0,%1,%2,%3}, {%4,%5,%6,%7}, {%8,%9}, {%0,%1,%2,%3};"
        : "+f"(d[0]), "+f"(d[1]), "+f"(d[2]), "+f"(d[3])
        : "r"(a[0]), "r"(a[1]), "r"(a[2]), "r"(a[3]), "r"(b[0]), "r"(b[1]));
}

// One 64x64 (i,j) upper-tri tile: gram via tensor cores (tf32 mma.sync) for all
// 8 (feature,batch) combos, fused batch-softmax + |A1-A2| epilogue.
// 8 warps = 4 positions (32x32) x 2 feature groups; probs exchanged via smem.
template<int C, int HW, int NT, int LVL_OFF>
__device__ __forceinline__ void gram_tile(const float* __restrict__ f1,
                                          const float* __restrict__ f2,
                                          int blk, uint32_t* smem)
{
    const int tid  = threadIdx.x;
    const int wid  = tid >> 5;
    const int lane = tid & 31;
    const int g    = wid >> 2;        // 0: feature1 combos, 1: feature2 combos
    const int pos  = wid & 3;
    const int pm   = pos >> 1;        // m half (32 rows)
    const int pn   = pos & 1;         // n half (32 cols)

    int rem = blk, ti = 0;
    while (rem >= NT - ti) { rem -= NT - ti; ti++; }
    const int tj = ti + rem;
    const int I0 = ti * 64;
    const int J0 = tj * 64;

    uint32_t* sA = smem;                       // [8 combos][KC][PADS]
    uint32_t* sB = smem + 8 * SIDE_STRIDE;

    const float* base_f = (g == 0) ? f1 : f2;

    // acc[batch][mt][nt][e]
    float acc[4][2][4][4];
    #pragma unroll
    for (int c = 0; c < 4; c++)
        #pragma unroll
        for (int mt = 0; mt < 2; mt++)
            #pragma unroll
            for (int nt = 0; nt < 4; nt++)
                #pragma unroll
                for (int e = 0; e < 4; e++) acc[c][mt][nt][e] = 0.f;

    const int lq = lane >> 2;   // 0..7
    const int lr = lane & 3;    // 0..3

    for (int k0 = 0; k0 < C; k0 += KC) {
        // ---- stage A and B (8 combos x KC k-rows x 64), cvt to tf32 ----
        #pragma unroll
        for (int it = 0; it < 8; it++) {
            int l = it * 256 + tid;
            int i4 = l & 15, kk = (l >> 4) & 15, combo = l >> 8;
            const float* src = (combo < 4) ? f1 : f2;
            const float* p = src + ((size_t)(combo & 3) * C + k0 + kk) * HW + I0 + i4 * 4;
            float4 v = *(const float4*)p;
            uint32_t* d = sA + combo * SIDE_STRIDE + kk * PADS + i4 * 4;
            d[0] = cvt_tf32(v.x); d[1] = cvt_tf32(v.y);
            d[2] = cvt_tf32(v.z); d[3] = cvt_tf32(v.w);
        }
        #pragma unroll
        for (int it = 0; it < 8; it++) {
            int l = it * 256 + tid;
            int j4 = l & 15, kk = (l >> 4) & 15, combo = l >> 8;
            const float* src = (combo < 4) ? f1 : f2;
            const float* p = src + ((size_t)(combo & 3) * C + k0 + kk) * HW + J0 + j4 * 4;
            float4 v = *(const float4*)p;
            uint32_t* d = sB + combo * SIDE_STRIDE + kk * PADS + j4 * 4;
            d[0] = cvt_tf32(v.x); d[1] = cvt_tf32(v.y);
            d[2] = cvt_tf32(v.z); d[3] = cvt_tf32(v.w);
        }
        __syncthreads();

        // ---- tensor-core compute: 2 k8 steps per chunk ----
        #pragma unroll
        for (int s = 0; s < 2; s++) {
            #pragma unroll
            for (int c = 0; c < 4; c++) {
                const uint32_t* cA = sA + (g * 4 + c) * SIDE_STRIDE;
                const uint32_t* cB = sB + (g * 4 + c) * SIDE_STRIDE;
                uint32_t afr[2][4], bfr[4][2];
                #pragma unroll
                for (int mt = 0; mt < 2; mt++)
                    #pragma unroll
                    for (int e = 0; e < 4; e++) {
                        int kk = s * 8 + lr + 4 * (e >> 1);
                        int i  = pm * 32 + mt * 16 + lq + 8 * (e & 1);
                        afr[mt][e] = cA[kk * PADS + i];
                    }
                #pragma unroll
                for (int nt = 0; nt < 4; nt++) {
                    int j = pn * 32 + nt * 8 + lq;
                    bfr[nt][0] = cB[(s * 8 + lr) * PADS + j];
                    bfr[nt][1] = cB[(s * 8 + lr + 4) * PADS + j];
                }
                #pragma unroll
                for (int mt = 0; mt < 2; mt++)
                    #pragma unroll
                    for (int nt = 0; nt < 4; nt++)
                        mma_tf32(acc[c][mt][nt], afr[mt], bfr[nt]);
            }
        }
        __syncthreads();
    }
    (void)base_f;

    // ---- epilogue: feature1 warps store softmax probs, feature2 warps diff ----
    float* ex = (float*)smem;   // 4 pos x 8 subtile x 4 e x 32 lane x 4 batch = 16384 floats
    if (g == 0) {
        #pragma unroll
        for (int mt = 0; mt < 2; mt++)
            #pragma unroll
            for (int nt = 0; nt < 4; nt++)
                #pragma unroll
                for (int e = 0; e < 4; e++) {
                    float x0 = acc[0][mt][nt][e], x1 = acc[1][mt][nt][e];
                    float x2 = acc[2][mt][nt][e], x3 = acc[3][mt][nt][e];
                    float m = fmaxf(fmaxf(x0, x1), fmaxf(x2, x3));
                    float e0 = __expf(x0 - m), e1 = __expf(x1 - m);
                    float e2 = __expf(x2 - m), e3 = __expf(x3 - m);
                    float s = 1.0f / (e0 + e1 + e2 + e3);
                    float4 pv = make_float4(e0 * s, e1 * s, e2 * s, e3 * s);
                    *(float4*)&ex[((((pos * 8 + mt * 4 + nt) * 4 + e) * 32 + lane) * 4)] = pv;
                }
    }
    __syncthreads();

    float lsum = 0.f;
    if (g == 1) {
        #pragma unroll
        for (int mt = 0; mt < 2; mt++)
            #pragma unroll
            for (int nt = 0; nt < 4; nt++)
                #pragma unroll
                for (int e = 0; e < 4; e++) {
                    const int gi = I0 + pm * 32 + mt * 16 + lq + 8 * (e >> 1);
                    const int gj = J0 + pn * 32 + nt * 8 + 2 * lr + (e & 1);
                    float w = (gi < gj) ? 2.f : ((gi == gj) ? 1.f : 0.f);
                    float y0 = acc[0][mt][nt][e], y1 = acc[1][mt][nt][e];
                    float y2 = acc[2][mt][nt][e], y3 = acc[3][mt][nt][e];
                    float m = fmaxf(fmaxf(y0, y1), fmaxf(y2, y3));
                    float h0 = __expf(y0 - m), h1 = __expf(y1 - m);
                    float h2 = __expf(y2 - m), h3 = __expf(y3 - m);
                    float s = 1.0f / (h0 + h1 + h2 + h3);
                    float4 pv = *(const float4*)&ex[((((pos * 8 + mt * 4 + nt) * 4 + e) * 32 + lane) * 4)];
                    lsum += w * (fabsf(pv.x - h0 * s) + fabsf(pv.y - h1 * s)
                               + fabsf(pv.z - h2 * s) + fabsf(pv.w - h3 * s));
                }
    }

    // Block reduction -> fixed partial slot (deterministic).
    #pragma unroll
    for (int o = 16; o > 0; o >>= 1) lsum += __shfl_xor_sync(0xffffffffu, lsum, o);
    __shared__ float red[8];
    if (lane == 0) red[wid] = lsum;
    __syncthreads();
    if (tid == 0) {
        float bs = 0.f;
        #pragma unroll
        for (int r = 0; r < 8; r++) bs += red[r];
        g_part[LVL_OFF + blk] = (double)bs;
    }
}

__global__ __launch_bounds__(256, 1)
void fused_gram_loss_kernel(const float* __restrict__ f1_0, const float* __restrict__ f2_0,
                            const float* __restrict__ f1_1, const float* __restrict__ f2_1)
{
    extern __shared__ uint32_t smem[];
    if (blockIdx.x < NBLK0)
        gram_tile<64, 4096, NTILE0, 0>(f1_0, f2_0, blockIdx.x, smem);
    else
        gram_tile<128, 1024, NTILE1, NBLK0>(f1_1, f2_1, blockIdx.x - NBLK0, smem);
}

__global__ void finalize_kernel(float* __restrict__ out)
{
    __shared__ double sd[256];
    const int tid = threadIdx.x;
    const double w0 = 0.5 / (4.0 * 4096.0 * 4096.0);
    const double w1 = 0.5 / (4.0 * 1024.0 * 1024.0);
    double s = 0.0;
    for (int i = tid; i < NBLK0; i += 256) s += g_part[i] * w0;
    for (int i = tid; i < NBLK1; i += 256) s += g_part[NBLK0 + i] * w1;
    sd[tid] = s;
    __syncthreads();
    for (int o = 128; o > 0; o >>= 1) {
        if (tid < o) sd[tid] += sd[tid + o];
        __syncthreads();
    }
    if (tid == 0) out[0] = (float)sd[0];
}

extern "C" void kernel_launch(void* const* d_in, const int* in_sizes, int n_in,
                              void* d_out, int out_size)
{
    const float* fea1_0 = (const float*)d_in[0];  // [4, 64, 64, 64]
    const float* fea1_1 = (const float*)d_in[1];  // [4, 128, 32, 32]
    const float* fea2_0 = (const float*)d_in[2];
    const float* fea2_1 = (const float*)d_in[3];
    float* out = (float*)d_out;

    cudaFuncSetAttribute(fused_gram_loss_kernel,
                         cudaFuncAttributeMaxDynamicSharedMemorySize, SMEM_BYTES);
    fused_gram_loss_kernel<<<NBLK0 + NBLK1, 256, SMEM_BYTES>>>(fea1_0, fea2_0, fea1_1, fea2_1);
    finalize_kernel<<<1, 256>>>(out);
}

// round 5
// speedup vs baseline: 2.0286x; 1.3038x over previous
#include <cuda_runtime.h>
#include <cstdint>
#include <math.h>

// Level 0: [4, 64, 4096], level 1: [4, 128, 1024]; 64x64 upper-tri tiles.
#define NTILE0 64
#define NTILE1 16
#define NBLK0 (NTILE0 * (NTILE0 + 1) / 2)   // 2080
#define NBLK1 (NTILE1 * (NTILE1 + 1) / 2)   // 136

#define KC 16                           // k-rows per chunk
#define PADS 72                         // 64 + 8 pad floats: banks (8*lr+lq) all distinct
#define SIDE_STRIDE (KC * PADS)         // 1152 floats per combo per side
#define BUF_FLOATS (16 * SIDE_STRIDE)   // A(8) + B(8) combos = 18432 floats
#define SMEM_BYTES (2 * BUF_FLOATS * 4) // double buffer: 147456 B

__device__ double g_part[NBLK0 + NBLK1];

__device__ __forceinline__ uint32_t smem_u32(const void* p) {
    return (uint32_t)__cvta_generic_to_shared(p);
}
__device__ __forceinline__ void cp16(uint32_t dst, const void* src) {
    asm volatile("cp.async.ca.shared.global [%0], [%1], 16;" :: "r"(dst), "l"(src));
}
#define CP_COMMIT() asm volatile("cp.async.commit_group;" ::: "memory")
#define CP_WAIT(n)  asm volatile("cp.async.wait_group %0;" :: "n"(n) : "memory")

__device__ __forceinline__ void mma_tf32(float* d, const uint32_t* a, const uint32_t* b) {
    asm volatile(
        "mma.sync.aligned.m16n8k8.row.col.f32.tf32.tf32.f32 "
        "{%0,%1,%2,%3}, {%4,%5,%6,%7}, {%8,%9}, {%0,%1,%2,%3};"
        : "+f"(d[0]), "+f"(d[1]), "+f"(d[2]), "+f"(d[3])
        : "r"(a[0]), "r"(a[1]), "r"(a[2]), "r"(a[3]), "r"(b[0]), "r"(b[1]));
}

// Stage one chunk (16 k-rows x 64 cols x 8 combos, both sides) via cp.async.
template<int C, int HW>
__device__ __forceinline__ void stage_chunk(const float* __restrict__ f1,
                                            const float* __restrict__ f2,
                                            int k0, int I0, int J0,
                                            uint32_t bufA_u, uint32_t bufB_u, int tid)
{
    #pragma unroll
    for (int it = 0; it < 8; it++) {
        int l = it * 256 + tid;
        int i4 = l & 15, kk = (l >> 4) & 15, combo = l >> 8;
        const float* src = (combo < 4) ? f1 : f2;
        const float* p = src + ((size_t)(combo & 3) * C + k0 + kk) * HW + I0 + i4 * 4;
        cp16(bufA_u + (combo * SIDE_STRIDE + kk * PADS + i4 * 4) * 4, p);
    }
    #pragma unroll
    for (int it = 0; it < 8; it++) {
        int l = it * 256 + tid;
        int j4 = l & 15, kk = (l >> 4) & 15, combo = l >> 8;
        const float* src = (combo < 4) ? f1 : f2;
        const float* p = src + ((size_t)(combo & 3) * C + k0 + kk) * HW + J0 + j4 * 4;
        cp16(bufB_u + (combo * SIDE_STRIDE + kk * PADS + j4 * 4) * 4, p);
    }
}

// One 64x64 (i,j) upper-tri tile: tf32 tensor-core gram for all 8
// (feature,batch) combos, cp.async double-buffered staging, fused
// batch-softmax + |A1-A2| epilogue. 8 warps = 4 positions x 2 features.
template<int C, int HW, int NT, int LVL_OFF>
__device__ __forceinline__ void gram_tile(const float* __restrict__ f1,
                                          const float* __restrict__ f2,
                                          int blk, uint32_t* smem)
{
    constexpr int CH = C / KC;
    const int tid  = threadIdx.x;
    const int wid  = tid >> 5;
    const int lane = tid & 31;
    const int g    = wid >> 2;        // 0: feature1, 1: feature2
    const int pos  = wid & 3;
    const int pm   = pos >> 1;
    const int pn   = pos & 1;

    int rem = blk, ti = 0;
    while (rem >= NT - ti) { rem -= NT - ti; ti++; }
    const int tj = ti + rem;
    const int I0 = ti * 64;
    const int J0 = tj * 64;

    const uint32_t smem_base = smem_u32(smem);

    float acc[4][2][4][4];
    #pragma unroll
    for (int c = 0; c < 4; c++)
        #pragma unroll
        for (int mt = 0; mt < 2; mt++)
            #pragma unroll
            for (int nt = 0; nt < 4; nt++)
                #pragma unroll
                for (int e = 0; e < 4; e++) acc[c][mt][nt][e] = 0.f;

    const int lq = lane >> 2;
    const int lr = lane & 3;

    // Prologue: stage chunk 0 into buffer 0.
    stage_chunk<C, HW>(f1, f2, 0, I0, J0,
                       smem_base, smem_base + 8 * SIDE_STRIDE * 4, tid);
    CP_COMMIT();

    for (int ch = 0; ch < CH; ch++) {
        // Issue next chunk into the other buffer before consuming this one.
        if (ch + 1 < CH) {
            uint32_t nb = smem_base + ((ch + 1) & 1) * BUF_FLOATS * 4;
            stage_chunk<C, HW>(f1, f2, (ch + 1) * KC, I0, J0,
                               nb, nb + 8 * SIDE_STRIDE * 4, tid);
            CP_COMMIT();
            CP_WAIT(1);             // chunk ch complete
        } else {
            CP_WAIT(0);
        }
        __syncthreads();

        const uint32_t* sA = smem + (ch & 1) * BUF_FLOATS;
        const uint32_t* sB = sA + 8 * SIDE_STRIDE;

        #pragma unroll
        for (int s = 0; s < 2; s++) {
            #pragma unroll
            for (int c = 0; c < 4; c++) {
                const uint32_t* cA = sA + (g * 4 + c) * SIDE_STRIDE;
                const uint32_t* cB = sB + (g * 4 + c) * SIDE_STRIDE;
                uint32_t afr[2][4], bfr[4][2];
                #pragma unroll
                for (int mt = 0; mt < 2; mt++)
                    #pragma unroll
                    for (int e = 0; e < 4; e++) {
                        int kk = s * 8 + lr + 4 * (e >> 1);
                        int i  = pm * 32 + mt * 16 + lq + 8 * (e & 1);
                        afr[mt][e] = cA[kk * PADS + i];
                    }
                #pragma unroll
                for (int nt = 0; nt < 4; nt++) {
                    int j = pn * 32 + nt * 8 + lq;
                    bfr[nt][0] = cB[(s * 8 + lr) * PADS + j];
                    bfr[nt][1] = cB[(s * 8 + lr + 4) * PADS + j];
                }
                #pragma unroll
                for (int mt = 0; mt < 2; mt++)
                    #pragma unroll
                    for (int nt = 0; nt < 4; nt++)
                        mma_tf32(acc[c][mt][nt], afr[mt], bfr[nt]);
            }
        }
        __syncthreads();   // all warps done reading before buffer reuse
    }

    // ---- epilogue: feature1 warps store softmax probs, feature2 warps diff ----
    float* ex = (float*)smem;   // 4 pos x 8 subtile x 4 e x 32 lane x 4 = 16384 floats
    if (g == 0) {
        #pragma unroll
        for (int mt = 0; mt < 2; mt++)
            #pragma unroll
            for (int nt = 0; nt < 4; nt++)
                #pragma unroll
                for (int e = 0; e < 4; e++) {
                    float x0 = acc[0][mt][nt][e], x1 = acc[1][mt][nt][e];
                    float x2 = acc[2][mt][nt][e], x3 = acc[3][mt][nt][e];
                    float m = fmaxf(fmaxf(x0, x1), fmaxf(x2, x3));
                    float e0 = __expf(x0 - m), e1 = __expf(x1 - m);
                    float e2 = __expf(x2 - m), e3 = __expf(x3 - m);
                    float s = 1.0f / (e0 + e1 + e2 + e3);
                    float4 pv = make_float4(e0 * s, e1 * s, e2 * s, e3 * s);
                    *(float4*)&ex[((((pos * 8 + mt * 4 + nt) * 4 + e) * 32 + lane) * 4)] = pv;
                }
    }
    __syncthreads();

    float lsum = 0.f;
    if (g == 1) {
        #pragma unroll
        for (int mt = 0; mt < 2; mt++)
            #pragma unroll
            for (int nt = 0; nt < 4; nt++)
                #pragma unroll
                for (int e = 0; e < 4; e++) {
                    const int gi = I0 + pm * 32 + mt * 16 + lq + 8 * (e >> 1);
                    const int gj = J0 + pn * 32 + nt * 8 + 2 * lr + (e & 1);
                    float w = (gi < gj) ? 2.f : ((gi == gj) ? 1.f : 0.f);
                    float y0 = acc[0][mt][nt][e], y1 = acc[1][mt][nt][e];
                    float y2 = acc[2][mt][nt][e], y3 = acc[3][mt][nt][e];
                    float m = fmaxf(fmaxf(y0, y1), fmaxf(y2, y3));
                    float h0 = __expf(y0 - m), h1 = __expf(y1 - m);
                    float h2 = __expf(y2 - m), h3 = __expf(y3 - m);
                    float s = 1.0f / (h0 + h1 + h2 + h3);
                    float4 pv = *(const float4*)&ex[((((pos * 8 + mt * 4 + nt) * 4 + e) * 32 + lane) * 4)];
                    lsum += w * (fabsf(pv.x - h0 * s) + fabsf(pv.y - h1 * s)
                               + fabsf(pv.z - h2 * s) + fabsf(pv.w - h3 * s));
                }
    }

    #pragma unroll
    for (int o = 16; o > 0; o >>= 1) lsum += __shfl_xor_sync(0xffffffffu, lsum, o);
    __shared__ float red[8];
    if (lane == 0) red[wid] = lsum;
    __syncthreads();
    if (tid == 0) {
        float bs = 0.f;
        #pragma unroll
        for (int r = 0; r < 8; r++) bs += red[r];
        g_part[LVL_OFF + blk] = (double)bs;
    }
}

// Level-1 CTAs (8 chunks, long) scheduled first to avoid a long tail wave.
__global__ __launch_bounds__(256, 1)
void fused_gram_loss_kernel(const float* __restrict__ f1_0, const float* __restrict__ f2_0,
                            const float* __restrict__ f1_1, const float* __restrict__ f2_1)
{
    extern __shared__ uint32_t smem[];
    if (blockIdx.x < NBLK1)
        gram_tile<128, 1024, NTILE1, NBLK0>(f1_1, f2_1, blockIdx.x, smem);
    else
        gram_tile<64, 4096, NTILE0, 0>(f1_0, f2_0, blockIdx.x - NBLK1, smem);
}

__global__ void finalize_kernel(float* __restrict__ out)
{
    __shared__ double sd[256];
    const int tid = threadIdx.x;
    const double w0 = 0.5 / (4.0 * 4096.0 * 4096.0);
    const double w1 = 0.5 / (4.0 * 1024.0 * 1024.0);
    double s = 0.0;
    for (int i = tid; i < NBLK0; i += 256) s += g_part[i] * w0;
    for (int i = tid; i < NBLK1; i += 256) s += g_part[NBLK0 + i] * w1;
    sd[tid] = s;
    __syncthreads();
    for (int o = 128; o > 0; o >>= 1) {
        if (tid < o) sd[tid] += sd[tid + o];
        __syncthreads();
    }
    if (tid == 0) out[0] = (float)sd[0];
}

extern "C" void kernel_launch(void* const* d_in, const int* in_sizes, int n_in,
                              void* d_out, int out_size)
{
    const float* fea1_0 = (const float*)d_in[0];  // [4, 64, 64, 64]
    const float* fea1_1 = (const float*)d_in[1];  // [4, 128, 32, 32]
    const float* fea2_0 = (const float*)d_in[2];
    const float* fea2_1 = (const float*)d_in[3];
    float* out = (float*)d_out;

    cudaFuncSetAttribute(fused_gram_loss_kernel,
                         cudaFuncAttributeMaxDynamicSharedMemorySize, SMEM_BYTES);
    fused_gram_loss_kernel<<<NBLK0 + NBLK1, 256, SMEM_BYTES>>>(fea1_0, fea2_0, fea1_1, fea2_1);
    finalize_kernel<<<1, 256>>>(out);
}

// round 6
// speedup vs baseline: 2.1395x; 1.0547x over previous
#include <cuda_runtime.h>
#include <cstdint>
#include <math.h>

// Level 0: [4, 64, 4096], level 1: [4, 128, 1024]; 64x64 upper-tri tiles.
#define NTILE0 64
#define NTILE1 16
#define NBLK0 (NTILE0 * (NTILE0 + 1) / 2)   // 2080
#define NBLK1 (NTILE1 * (NTILE1 + 1) / 2)   // 136
#define NBLK  (NBLK0 + NBLK1)

#define KC 16                           // k-rows per chunk
#define PADS 72                         // 64 + 8 pad floats: frag banks (8*lr+lq) all distinct
#define SIDE_STRIDE (KC * PADS)         // 1152 floats per combo per side
#define BUF_FLOATS (16 * SIDE_STRIDE)   // A(8) + B(8) combos = 18432 floats
#define SMEM_BYTES (2 * BUF_FLOATS * 4) // double buffer: 147456 B

__device__ double g_sum = 0.0;
__device__ unsigned g_cnt = 0u;

__device__ __forceinline__ uint32_t smem_u32(const void* p) {
    return (uint32_t)__cvta_generic_to_shared(p);
}
__device__ __forceinline__ void cp16(uint32_t dst, const void* src) {
    asm volatile("cp.async.ca.shared.global [%0], [%1], 16;" :: "r"(dst), "l"(src));
}
#define CP_COMMIT() asm volatile("cp.async.commit_group;" ::: "memory")
#define CP_WAIT(n)  asm volatile("cp.async.wait_group %0;" :: "n"(n) : "memory")

__device__ __forceinline__ void mma_tf32(float* d, const uint32_t* a, const uint32_t* b) {
    asm volatile(
        "mma.sync.aligned.m16n8k8.row.col.f32.tf32.tf32.f32 "
        "{%0,%1,%2,%3}, {%4,%5,%6,%7}, {%8,%9}, {%0,%1,%2,%3};"
        : "+f"(d[0]), "+f"(d[1]), "+f"(d[2]), "+f"(d[3])
        : "r"(a[0]), "r"(a[1]), "r"(a[2]), "r"(a[3]), "r"(b[0]), "r"(b[1]));
}

// Stage one chunk (16 k-rows x 64 cols x 8 combos, both sides), 512 threads.
template<int C, int HW>
__device__ __forceinline__ void stage_chunk(const float* __restrict__ f1,
                                            const float* __restrict__ f2,
                                            int k0, int I0, int J0,
                                            uint32_t bufA_u, uint32_t bufB_u, int tid)
{
    #pragma unroll
    for (int it = 0; it < 4; it++) {
        int l = it * 512 + tid;
        int i4 = l & 15, kk = (l >> 4) & 15, combo = l >> 8;
        const float* src = (combo < 4) ? f1 : f2;
        const float* p = src + ((size_t)(combo & 3) * C + k0 + kk) * HW + I0 + i4 * 4;
        cp16(bufA_u + (combo * SIDE_STRIDE + kk * PADS + i4 * 4) * 4, p);
    }
    #pragma unroll
    for (int it = 0; it < 4; it++) {
        int l = it * 512 + tid;
        int j4 = l & 15, kk = (l >> 4) & 15, combo = l >> 8;
        const float* src = (combo < 4) ? f1 : f2;
        const float* p = src + ((size_t)(combo & 3) * C + k0 + kk) * HW + J0 + j4 * 4;
        cp16(bufB_u + (combo * SIDE_STRIDE + kk * PADS + j4 * 4) * 4, p);
    }
}

// One 64x64 (i,j) upper-tri tile. 16 warps = 8 spatial patches (32x16) x 2
// features; each warp holds all 4 batches of its patch -> in-warp softmax.
// Probs of feature1 exchanged through smem; single extra sync.
template<int C, int HW, int NT>
__device__ __forceinline__ void gram_tile(const float* __restrict__ f1,
                                          const float* __restrict__ f2,
                                          int blk, uint32_t* smem,
                                          double lvl_w, float* out)
{
    constexpr int CH = C / KC;
    const int tid  = threadIdx.x;
    const int wid  = tid >> 5;
    const int lane = tid & 31;
    const int g    = wid >> 3;        // 0: feature1, 1: feature2
    const int pos  = wid & 7;
    const int pm   = pos >> 2;        // 2 x 32-row halves
    const int pn   = pos & 3;         // 4 x 16-col strips

    int rem = blk, ti = 0;
    while (rem >= NT - ti) { rem -= NT - ti; ti++; }
    const int tj = ti + rem;
    const int I0 = ti * 64;
    const int J0 = tj * 64;

    const uint32_t smem_base = smem_u32(smem);

    float acc[4][2][2][4];   // [batch][mt][nt][e]
    #pragma unroll
    for (int c = 0; c < 4; c++)
        #pragma unroll
        for (int mt = 0; mt < 2; mt++)
            #pragma unroll
            for (int nt = 0; nt < 2; nt++)
                #pragma unroll
                for (int e = 0; e < 4; e++) acc[c][mt][nt][e] = 0.f;

    const int lq = lane >> 2;
    const int lr = lane & 3;

    stage_chunk<C, HW>(f1, f2, 0, I0, J0,
                       smem_base, smem_base + 8 * SIDE_STRIDE * 4, tid);
    CP_COMMIT();

    for (int ch = 0; ch < CH; ch++) {
        if (ch + 1 < CH) {
            uint32_t nb = smem_base + ((ch + 1) & 1) * BUF_FLOATS * 4;
            stage_chunk<C, HW>(f1, f2, (ch + 1) * KC, I0, J0,
                               nb, nb + 8 * SIDE_STRIDE * 4, tid);
            CP_COMMIT();
            CP_WAIT(1);
        } else {
            CP_WAIT(0);
        }
        __syncthreads();

        const uint32_t* sA = smem + (ch & 1) * BUF_FLOATS;
        const uint32_t* sB = sA + 8 * SIDE_STRIDE;

        #pragma unroll
        for (int s = 0; s < 2; s++) {
            #pragma unroll
            for (int c = 0; c < 4; c++) {
                const uint32_t* cA = sA + (g * 4 + c) * SIDE_STRIDE;
                const uint32_t* cB = sB + (g * 4 + c) * SIDE_STRIDE;
                uint32_t afr[2][4], bfr[2][2];
                #pragma unroll
                for (int mt = 0; mt < 2; mt++)
                    #pragma unroll
                    for (int e = 0; e < 4; e++) {
                        int kk = s * 8 + lr + 4 * (e >> 1);
                        int i  = pm * 32 + mt * 16 + lq + 8 * (e & 1);
                        afr[mt][e] = cA[kk * PADS + i];
                    }
                #pragma unroll
                for (int nt = 0; nt < 2; nt++) {
                    int j = pn * 16 + nt * 8 + lq;
                    bfr[nt][0] = cB[(s * 8 + lr) * PADS + j];
                    bfr[nt][1] = cB[(s * 8 + lr + 4) * PADS + j];
                }
                #pragma unroll
                for (int mt = 0; mt < 2; mt++)
                    #pragma unroll
                    for (int nt = 0; nt < 2; nt++)
                        mma_tf32(acc[c][mt][nt], afr[mt], bfr[nt]);
            }
        }
        __syncthreads();
    }

    // ---- epilogue ----
    float* ex = (float*)smem;   // 8 pos x 16 subtile x 32 lane x 4 batch = 16384 floats
    if (g == 0) {
        #pragma unroll
        for (int mt = 0; mt < 2; mt++)
            #pragma unroll
            for (int nt = 0; nt < 2; nt++)
                #pragma unroll
                for (int e = 0; e < 4; e++) {
                    float x0 = acc[0][mt][nt][e], x1 = acc[1][mt][nt][e];
                    float x2 = acc[2][mt][nt][e], x3 = acc[3][mt][nt][e];
                    float m = fmaxf(fmaxf(x0, x1), fmaxf(x2, x3));
                    float e0 = __expf(x0 - m), e1 = __expf(x1 - m);
                    float e2 = __expf(x2 - m), e3 = __expf(x3 - m);
                    float s = 1.0f / (e0 + e1 + e2 + e3);
                    int sub = (mt * 2 + nt) * 4 + e;
                    *(float4*)&ex[((pos * 16 + sub) * 32 + lane) * 4] =
                        make_float4(e0 * s, e1 * s, e2 * s, e3 * s);
                }
    }
    __syncthreads();

    float lsum = 0.f;
    if (g == 1) {
        #pragma unroll
        for (int mt = 0; mt < 2; mt++)
            #pragma unroll
            for (int nt = 0; nt < 2; nt++)
                #pragma unroll
                for (int e = 0; e < 4; e++) {
                    const int gi = I0 + pm * 32 + mt * 16 + lq + 8 * (e >> 1);
                    const int gj = J0 + pn * 16 + nt * 8 + 2 * lr + (e & 1);
                    float w = (gi < gj) ? 2.f : ((gi == gj) ? 1.f : 0.f);
                    float y0 = acc[0][mt][nt][e], y1 = acc[1][mt][nt][e];
                    float y2 = acc[2][mt][nt][e], y3 = acc[3][mt][nt][e];
                    float m = fmaxf(fmaxf(y0, y1), fmaxf(y2, y3));
                    float h0 = __expf(y0 - m), h1 = __expf(y1 - m);
                    float h2 = __expf(y2 - m), h3 = __expf(y3 - m);
                    float s = 1.0f / (h0 + h1 + h2 + h3);
                    int sub = (mt * 2 + nt) * 4 + e;
                    float4 pv = *(const float4*)&ex[((pos * 16 + sub) * 32 + lane) * 4];
                    lsum += w * (fabsf(pv.x - h0 * s) + fabsf(pv.y - h1 * s)
                               + fabsf(pv.z - h2 * s) + fabsf(pv.w - h3 * s));
                }
    }

    #pragma unroll
    for (int o = 16; o > 0; o >>= 1) lsum += __shfl_xor_sync(0xffffffffu, lsum, o);
    __shared__ float red[16];
    if (lane == 0) red[wid] = lsum;
    __syncthreads();
    if (tid == 0) {
        float bs = 0.f;
        #pragma unroll
        for (int r = 0; r < 16; r++) bs += red[r];
        atomicAdd(&g_sum, (double)bs * lvl_w);
        __threadfence();
        unsigned t = atomicAdd(&g_cnt, 1u);
        if (t == (unsigned)(NBLK - 1)) {
            out[0] = (float)g_sum;     // all partials visible (counter + fence)
            g_sum = 0.0;               // reset for next graph replay
            g_cnt = 0u;
        }
    }
}

// Level-1 CTAs (8 chunks, long) scheduled first to avoid a long tail wave.
__global__ __launch_bounds__(512, 1)
void fused_gram_loss_kernel(const float* __restrict__ f1_0, const float* __restrict__ f2_0,
                            const float* __restrict__ f1_1, const float* __restrict__ f2_1,
                            float* __restrict__ out)
{
    extern __shared__ uint32_t smem[];
    const double w0 = 0.5 / (4.0 * 4096.0 * 4096.0);
    const double w1 = 0.5 / (4.0 * 1024.0 * 1024.0);
    if (blockIdx.x < NBLK1)
        gram_tile<128, 1024, NTILE1>(f1_1, f2_1, blockIdx.x, smem, w1, out);
    else
        gram_tile<64, 4096, NTILE0>(f1_0, f2_0, blockIdx.x - NBLK1, smem, w0, out);
}

extern "C" void kernel_launch(void* const* d_in, const int* in_sizes, int n_in,
                              void* d_out, int out_size)
{
    const float* fea1_0 = (const float*)d_in[0];  // [4, 64, 64, 64]
    const float* fea1_1 = (const float*)d_in[1];  // [4, 128, 32, 32]
    const float* fea2_0 = (const float*)d_in[2];
    const float* fea2_1 = (const float*)d_in[3];
    float* out = (float*)d_out;

    cudaFuncSetAttribute(fused_gram_loss_kernel,
                         cudaFuncAttributeMaxDynamicSharedMemorySize, SMEM_BYTES);
    fused_gram_loss_kernel<<<NBLK, 512, SMEM_BYTES>>>(fea1_0, fea2_0, fea1_1, fea2_1, out);
}